// round 15
// baseline (speedup 1.0000x reference)
#include <cuda_runtime.h>

#define BB 16
#define TT 128
#define DD 1024
#define EE 128
#define HHN 128
#define GG 384           // 3*H
#define NSEQ (BB*TT)     // 2048
#define NG8  256         // groups of 8 seqs (2 per time position i)

// scan smem layout (floats)
#define OFF_H   49152                   // 2 x 8 x 132 hidden-state buffers
#define SMEM_FLOATS (OFF_H + 2*8*132)   // 51264 floats = 205056 B

// ---------------- scratch (device globals; no allocation) ----------------
__device__ float g_emb [NSEQ*EE];
__device__ float g_wemb[NSEQ*EE];       // Wo[e]*emb
__device__ float g_GXa [NSEQ*GG];
__device__ float g_GXb [NSEQ*GG];
__device__ float g_pa  [NSEQ*TT];       // pre_alpha[n][k]
__device__ float g_sv  [NSEQ*TT];       // s[n][k]
__device__ float g_hsa [(size_t)TT*NSEQ*HHN];   // h_a[k][n][h]
__device__ float g_hsb [(size_t)TT*NSEQ*HHN];   // h_b[k][n][h]

typedef unsigned long long ull;

__device__ __forceinline__ void ffma2(ull &d, ull a, ull b) {
    asm("fma.rn.f32x2 %0, %1, %2, %0;" : "+l"(d) : "l"(a), "l"(b));
}
__device__ __forceinline__ void lds128v(unsigned a, ull &p0, ull &p1) {
    asm volatile("ld.shared.v2.b64 {%0,%1}, [%2];" : "=l"(p0), "=l"(p1) : "r"(a));
}
__device__ __forceinline__ float pairsum(ull v) {
    return __uint_as_float((unsigned)v) + __uint_as_float((unsigned)(v >> 32));
}
__device__ __forceinline__ ull dup2(float x) {
    ull v; asm("mov.b64 %0, {%1,%1};" : "=l"(v) : "f"(x)); return v;
}
__device__ __forceinline__ float tanhhw(float x) {
    float y; asm("tanh.approx.f32 %0, %1;" : "=f"(y) : "f"(x)); return y;
}

// ---------------- Kernel 1: emb = x @ W_emb^T ; wemb = Wo .* emb ----------------
__global__ __launch_bounds__(256) void emb_kernel(
    const float* __restrict__ x, const float* __restrict__ Wemb,
    const float* __restrict__ Wo)
{
    __shared__ float sx[16][68];
    __shared__ float sw[16][36];
    int tid = threadIdx.x;
    int m0 = blockIdx.x * 64;
    int n0 = blockIdx.y * 32;
    int tx = tid & 15, ty = tid >> 4;
    int tm0 = tx * 4, tn0 = ty * 2;

    float acc[4][2];
#pragma unroll
    for (int q = 0; q < 4; q++) { acc[q][0] = 0.f; acc[q][1] = 0.f; }

    for (int kt = 0; kt < DD; kt += 16) {
        {
            int e = tid * 4; int m = e >> 4; int k = e & 15;
            float4 v = *(const float4*)(x + (size_t)(m0 + m) * DD + kt + k);
            sx[k][m] = v.x; sx[k+1][m] = v.y; sx[k+2][m] = v.z; sx[k+3][m] = v.w;
        }
        {
            int e = tid * 2; int n = e >> 4; int k = e & 15;
            float2 v = *(const float2*)(Wemb + (size_t)(n0 + n) * DD + kt + k);
            sw[k][n] = v.x; sw[k+1][n] = v.y;
        }
        __syncthreads();
#pragma unroll
        for (int k = 0; k < 16; k++) {
            float a0 = sx[k][tm0], a1 = sx[k][tm0+1], a2 = sx[k][tm0+2], a3 = sx[k][tm0+3];
            float b0 = sw[k][tn0], b1 = sw[k][tn0+1];
            acc[0][0] += a0*b0; acc[0][1] += a0*b1;
            acc[1][0] += a1*b0; acc[1][1] += a1*b1;
            acc[2][0] += a2*b0; acc[2][1] += a2*b1;
            acc[3][0] += a3*b0; acc[3][1] += a3*b1;
        }
        __syncthreads();
    }
#pragma unroll
    for (int q = 0; q < 4; q++)
#pragma unroll
        for (int r = 0; r < 2; r++) {
            int m = m0 + tm0 + q, n = n0 + tn0 + r;
            float v = acc[q][r];
            g_emb [m*EE + n] = v;
            g_wemb[m*EE + n] = v * Wo[n];
        }
}

// ---------------- Kernel 2: GX = emb @ Wih^T + bih (both GRUs) ----------------
__global__ __launch_bounds__(256) void gx_kernel(
    const float* __restrict__ Wih_a, const float* __restrict__ Wih_b,
    const float* __restrict__ bih_a, const float* __restrict__ bih_b)
{
    __shared__ float se [16][68];
    __shared__ float sw2[16][68];
    int tid = threadIdx.x;
    int m0 = blockIdx.x * 64;
    int n0 = blockIdx.y * 64;
    int tx = tid & 15, ty = tid >> 4;
    int tm0 = tx * 4, tn0 = ty * 4;

    const float* W; const float* bi; float* out; int nb;
    if (n0 < GG) { W = Wih_a; bi = bih_a; out = g_GXa; nb = n0; }
    else         { W = Wih_b; bi = bih_b; out = g_GXb; nb = n0 - GG; }

    float acc[4][4];
#pragma unroll
    for (int q = 0; q < 4; q++)
#pragma unroll
        for (int r = 0; r < 4; r++) acc[q][r] = 0.f;

    for (int kt = 0; kt < EE; kt += 16) {
        {
            int e = tid * 4; int m = e >> 4; int k = e & 15;
            float4 v = *(const float4*)(g_emb + (size_t)(m0 + m) * EE + kt + k);
            se[k][m] = v.x; se[k+1][m] = v.y; se[k+2][m] = v.z; se[k+3][m] = v.w;
        }
        {
            int e = tid * 4; int n = e >> 4; int k = e & 15;
            float4 v = *(const float4*)(W + (size_t)(nb + n) * EE + kt + k);
            sw2[k][n] = v.x; sw2[k+1][n] = v.y; sw2[k+2][n] = v.z; sw2[k+3][n] = v.w;
        }
        __syncthreads();
#pragma unroll
        for (int k = 0; k < 16; k++) {
            float a[4], b[4];
#pragma unroll
            for (int q = 0; q < 4; q++) a[q] = se[k][tm0+q];
#pragma unroll
            for (int r = 0; r < 4; r++) b[r] = sw2[k][tn0+r];
#pragma unroll
            for (int q = 0; q < 4; q++)
#pragma unroll
                for (int r = 0; r < 4; r++) acc[q][r] += a[q]*b[r];
        }
        __syncthreads();
    }
#pragma unroll
    for (int q = 0; q < 4; q++)
#pragma unroll
        for (int r = 0; r < 4; r++) {
            int m = m0 + tm0 + q, n = nb + tn0 + r;
            out[(size_t)m*GG + n] = acc[q][r] + bi[n];
        }
}

// ---------------- Kernel 3: persistent GRU scan (EXACT R10, best: 589us) ------
__global__ __launch_bounds__(256, 1) void scan_kernel(
    const float* __restrict__ Whh_a, const float* __restrict__ Whh_b,
    const float* __restrict__ bhh_a, const float* __restrict__ bhh_b,
    int RA, int Rtot)
{
    extern __shared__ float smem[];
    float* shv = smem + OFF_H;

    unsigned sbase;
    asm("{ .reg .u64 t; cvta.to.shared.u64 t, %1; cvt.u32.u64 %0, t; }"
        : "=r"(sbase) : "l"(smem));
    unsigned shH = sbase + OFF_H * 4;      // h buffers: 2 x (8 x 132 floats)

    int tid = threadIdx.x;
    int lane = tid & 31, w = tid >> 5;
    int u = (w << 4) + (lane >> 1);
    int parity = lane & 1;
    int sqb = parity * 4;                  // my 4 seqs: sqb..sqb+3
    bool roleA = (blockIdx.x < RA);
    int rc = roleA ? blockIdx.x : blockIdx.x - RA;
    int R  = roleA ? RA : (Rtot - RA);

    const float* Whh = roleA ? Whh_a : Whh_b;
    const float* bhh = roleA ? bhh_a : bhh_b;
    const float* GX  = roleA ? g_GXa : g_GXb;
    float* HS        = roleA ? g_hsa : g_hsb;

    // stage all weight pairs into SMEM, ull2 entries e = (g*32+pp)*128 + u
    {
        const ull* W2 = (const ull*)Whh;
        ull* sz = (ull*)smem;
        for (int e = tid; e < 12288; e += 256) {
            int uu = e & 127;
            int pp = (e >> 7) & 31;
            int g  = e >> 12;
            const ull* src = W2 + (size_t)(g*128 + uu)*64 + 2*pp;
            sz[2*e]   = src[0];
            sz[2*e+1] = src[1];
        }
    }
    float bhr = bhh[u], bhz = bhh[128 + u], bhn = bhh[256 + u];

    unsigned wbR = sbase + (unsigned)u * 16;     // + pp*2048
    unsigned wbZ = wbR + 65536;
    unsigned wbN = wbZ + 65536;
    __syncthreads();

    for (int mIdx = 0;; mIdx++) {
        int g = mIdx*R + ((mIdx & 1) ? (R - 1 - rc) : rc);   // snake
        if (g >= NG8) break;

        int i  = 127 - (g >> 1);      // longest-first
        int b0 = (g & 1) * 8;

        __syncthreads();              // protect buffers vs previous group
        for (int idx = tid; idx < 8*132; idx += 256) shv[idx] = 0.f;  // buf0
        __syncthreads();

        float hold[4];
#pragma unroll
        for (int ss = 0; ss < 4; ss++) hold[ss] = 0.f;

        for (int k = 0; k <= i; k++) {
            int j = i - k;
            float gir[4], giz[4], gin[4];
#pragma unroll
            for (int ss = 0; ss < 4; ss++) {
                const float* p = GX + (size_t)((b0 + sqb + ss)*TT + j)*GG + u;
                gir[ss] = __ldg(p);
                giz[ss] = __ldg(p + 128);
                gin[ss] = __ldg(p + 256);
            }

            unsigned hb = shH + (unsigned)((k & 1) * 8*132) * 4
                              + (unsigned)sqb * 528;
            ull ar[4], az[4], an[4];
#pragma unroll
            for (int ss = 0; ss < 4; ss++) { ar[ss] = 0; az[ss] = 0; an[ss] = 0; }
#pragma unroll
            for (int pp = 0; pp < 32; pp++) {
                ull wr0, wr1, wz0, wz1, wn0, wn1;
                lds128v(wbR + (unsigned)pp*2048, wr0, wr1);
                lds128v(wbZ + (unsigned)pp*2048, wz0, wz1);
                lds128v(wbN + (unsigned)pp*2048, wn0, wn1);
#pragma unroll
                for (int ss = 0; ss < 4; ss++) {
                    ull p0, p1;
                    lds128v(hb + (unsigned)(ss*528 + pp*16), p0, p1);
                    ffma2(ar[ss], wr0, p0); ffma2(ar[ss], wr1, p1);
                    ffma2(az[ss], wz0, p0); ffma2(az[ss], wz1, p1);
                    ffma2(an[ss], wn0, p0); ffma2(an[ss], wn1, p1);
                }
            }

            int bufn = ((k + 1) & 1) * 8 * 132;
#pragma unroll
            for (int ss = 0; ss < 4; ss++) {
                int s = sqb + ss;
                float fr = pairsum(ar[ss]) + gir[ss] + bhr;
                float fz = pairsum(az[ss]) + giz[ss] + bhz;
                float fn = pairsum(an[ss]) + bhn;
                float rr = 0.5f + 0.5f * tanhhw(0.5f * fr);
                float zz = 0.5f + 0.5f * tanhhw(0.5f * fz);
                float nn = tanhhw(gin[ss] + rr * fn);
                float h2 = (1.f - zz)*nn + zz*hold[ss];
                hold[ss] = h2;
                shv[bufn + s*132 + u] = h2;
                HS[((size_t)k*NSEQ + (b0 + s)*TT + i)*HHN + u] = h2;
            }
            __syncthreads();
        } // k
    } // groups
}

// ---------------- Kernel 4: beta GEMM + wemb dot + alpha fold -> s, pa --------
// R10 beta structure; additionally computes pre_alpha[n][k] = 0.5*Wa.h_a + ba
// for its 64 n (deletes the standalone alpha kernel).
__global__ __launch_bounds__(256) void beta_kernel(
    const float* __restrict__ Wb, const float* __restrict__ bb,
    const float* __restrict__ Wa, const float* __restrict__ ba)
{
    int k  = blockIdx.x;          // 0..127
    int nb = blockIdx.y;          // 0..31
    int i0 = (nb & 1) * 64;
    if (i0 + 63 < k) return;
    int n0 = nb * 64;
    int b  = n0 >> 7;

    __shared__ float shh[16][68];
    __shared__ float sww[16][132];
    __shared__ float red[64][17];

    int tid = threadIdx.x;
    int tx = tid & 15, ty = tid >> 4;
    int r0 = tx * 4, e0 = ty * 8;

    const float* hb = g_hsb + ((size_t)k*NSEQ + n0)*HHN;

    // ---- alpha fold: pa[n][k] for my 64 n (quad-split dot over h) ----
    {
        int nl = tid >> 2, quad = tid & 3;
        int n = n0 + nl;
        const float* ha = g_hsa + ((size_t)k*NSEQ + n)*HHN + quad*32;
        float p = 0.f;
#pragma unroll
        for (int q = 0; q < 8; q++) {
            float4 v  = *(const float4*)(ha + q*4);
            float4 wv = *(const float4*)(Wa + quad*32 + q*4);
            p += v.x*wv.x + v.y*wv.y + v.z*wv.z + v.w*wv.w;
        }
        p += __shfl_xor_sync(0xffffffffu, p, 1);
        p += __shfl_xor_sync(0xffffffffu, p, 2);
        int i = n & 127;
        if (quad == 0 && k <= i)
            g_pa[(size_t)n*TT + k] = 0.5f*p + ba[0];
    }

    ull acc2[4][4];
#pragma unroll
    for (int q = 0; q < 4; q++)
#pragma unroll
        for (int e = 0; e < 4; e++) acc2[q][e] = 0;

    for (int kt = 0; kt < HHN; kt += 16) {
        {
            int e = tid * 4; int rr = e >> 4; int h = e & 15;
            float4 v = *(const float4*)(hb + (size_t)rr*HHN + kt + h);
            shh[h][rr] = v.x; shh[h+1][rr] = v.y; shh[h+2][rr] = v.z; shh[h+3][rr] = v.w;
        }
        {
            int e2 = tid * 8; int ee = e2 >> 4; int h = e2 & 15;
            float4 v0 = *(const float4*)(Wb + (size_t)ee*HHN + kt + h);
            float4 v1 = *(const float4*)(Wb + (size_t)ee*HHN + kt + h + 4);
            sww[h  ][ee] = 0.5f*v0.x; sww[h+1][ee] = 0.5f*v0.y;
            sww[h+2][ee] = 0.5f*v0.z; sww[h+3][ee] = 0.5f*v0.w;
            sww[h+4][ee] = 0.5f*v1.x; sww[h+5][ee] = 0.5f*v1.y;
            sww[h+6][ee] = 0.5f*v1.z; sww[h+7][ee] = 0.5f*v1.w;
        }
        __syncthreads();
#pragma unroll
        for (int kk = 0; kk < 16; kk++) {
            ull av[4], bv[4];
#pragma unroll
            for (int q = 0; q < 4; q++) av[q] = dup2(shh[kk][r0+q]);
            const ull* bp = (const ull*)&sww[kk][e0];
#pragma unroll
            for (int e = 0; e < 4; e++) bv[e] = bp[e];
#pragma unroll
            for (int q = 0; q < 4; q++)
#pragma unroll
                for (int e = 0; e < 4; e++) ffma2(acc2[q][e], av[q], bv[e]);
        }
        __syncthreads();
    }

    float bbv[8];
#pragma unroll
    for (int e = 0; e < 8; e++) bbv[e] = bb[e0 + e];

#pragma unroll
    for (int q = 0; q < 4; q++) {
        int n = n0 + r0 + q;
        int i = n & 127;
        int j = i - k;
        const float* wm = g_wemb + ((size_t)b*TT + (j >= 0 ? j : 0))*EE + e0;
        float p = 0.f;
#pragma unroll
        for (int e = 0; e < 4; e++) {
            float lo = __uint_as_float((unsigned)acc2[q][e]);
            float hi = __uint_as_float((unsigned)(acc2[q][e] >> 32));
            p += tanhhw(lo + bbv[2*e])   * wm[2*e];
            p += tanhhw(hi + bbv[2*e+1]) * wm[2*e+1];
        }
        red[r0 + q][ty] = p;
    }
    __syncthreads();
    if (tid < 64) {
        float v = 0.f;
#pragma unroll
        for (int t = 0; t < 16; t++) v += red[tid][t];
        int n = n0 + tid;
        int i = n & 127;
        if (k <= i) g_sv[(size_t)n*TT + k] = v;
    }
}

// ---------------- Kernel 5: masked softmax combine ----------------
__global__ __launch_bounds__(256) void combine_kernel(
    const float* __restrict__ bo, float* __restrict__ out)
{
    int w = blockIdx.x * 8 + (threadIdx.x >> 5);
    int lane = threadIdx.x & 31;
    if (w >= NSEQ) return;
    int i = w & 127;
    float num = 0.f, den = 0.f;
    for (int k = lane; k <= i; k += 32) {
        float ev = __expf(g_pa[(size_t)w*TT + k]);
        num += ev * g_sv[(size_t)w*TT + k];
        den += ev;
    }
#pragma unroll
    for (int o = 16; o > 0; o >>= 1) {
        num += __shfl_xor_sync(0xffffffffu, num, o);
        den += __shfl_xor_sync(0xffffffffu, den, o);
    }
    if (lane == 0) out[w] = num / den + bo[0];
}

// ---------------- launch ----------------
extern "C" void kernel_launch(void* const* d_in, const int* in_sizes, int n_in,
                              void* d_out, int out_size)
{
    const float* x     = (const float*)d_in[0];
    const float* Wemb  = (const float*)d_in[1];
    const float* Wih_a = (const float*)d_in[2];
    const float* Whh_a = (const float*)d_in[3];
    const float* bih_a = (const float*)d_in[4];
    const float* bhh_a = (const float*)d_in[5];
    const float* Wa    = (const float*)d_in[6];
    const float* ba    = (const float*)d_in[7];
    const float* Wih_b = (const float*)d_in[8];
    const float* Whh_b = (const float*)d_in[9];
    const float* bih_b = (const float*)d_in[10];
    const float* bhh_b = (const float*)d_in[11];
    const float* Wb    = (const float*)d_in[12];
    const float* bb    = (const float*)d_in[13];
    const float* Wo    = (const float*)d_in[14];
    const float* bo    = (const float*)d_in[15];
    float* out = (float*)d_out;

    int dev = 0;
    cudaGetDevice(&dev);
    int sms = 148;
    cudaDeviceGetAttribute(&sms, cudaDevAttrMultiProcessorCount, dev);
    int RA = sms / 2;

    size_t smem_bytes = (size_t)SMEM_FLOATS * sizeof(float);
    cudaFuncSetAttribute(scan_kernel,
                         cudaFuncAttributeMaxDynamicSharedMemorySize,
                         (int)smem_bytes);

    emb_kernel<<<dim3(32, 4), 256>>>(x, Wemb, Wo);
    gx_kernel<<<dim3(32, 12), 256>>>(Wih_a, Wih_b, bih_a, bih_b);
    scan_kernel<<<sms, 256, smem_bytes>>>(Whh_a, Whh_b, bhh_a, bhh_b, RA, sms);
    beta_kernel<<<dim3(TT, NSEQ/64), 256>>>(Wb, bb, Wa, ba);
    combine_kernel<<<NSEQ/8, 256>>>(bo, out);
}

// round 16
// speedup vs baseline: 1.6543x; 1.6543x over previous
#include <cuda_runtime.h>

#define BB 16
#define TT 128
#define DD 1024
#define EE 128
#define HHN 128
#define GG 384           // 3*H
#define NSEQ (BB*TT)     // 2048
#define NG8  256         // groups of 8 seqs (2 per time position i)

// scan smem layout (floats)
#define OFF_H   49152                   // 2 x 8 x 132 hidden-state buffers
#define SMEM_FLOATS (OFF_H + 2*8*132)   // 51264 floats = 205056 B

// ---------------- scratch (device globals; no allocation) ----------------
__device__ float g_emb [NSEQ*EE];
__device__ float g_wemb[NSEQ*EE];       // Wo[e]*emb
__device__ float g_GXa [NSEQ*GG];
__device__ float g_GXb [NSEQ*GG];
__device__ float g_pa  [NSEQ*TT];       // pre_alpha[n][k]
__device__ float g_sv  [NSEQ*TT];       // s[n][k]
__device__ float g_hsa [(size_t)TT*NSEQ*HHN];   // h_a[k][n][h]
__device__ float g_hsb [(size_t)TT*NSEQ*HHN];   // h_b[k][n][h]

typedef unsigned long long ull;

__device__ __forceinline__ void ffma2(ull &d, ull a, ull b) {
    asm("fma.rn.f32x2 %0, %1, %2, %0;" : "+l"(d) : "l"(a), "l"(b));
}
__device__ __forceinline__ void lds128v(unsigned a, ull &p0, ull &p1) {
    asm volatile("ld.shared.v2.b64 {%0,%1}, [%2];" : "=l"(p0), "=l"(p1) : "r"(a));
}
__device__ __forceinline__ float pairsum(ull v) {
    return __uint_as_float((unsigned)v) + __uint_as_float((unsigned)(v >> 32));
}
__device__ __forceinline__ ull dup2(float x) {
    ull v; asm("mov.b64 %0, {%1,%1};" : "=l"(v) : "f"(x)); return v;
}
__device__ __forceinline__ float tanhhw(float x) {
    float y; asm("tanh.approx.f32 %0, %1;" : "=f"(y) : "f"(x)); return y;
}

// ---------------- Kernel 1: emb = x @ W_emb^T ; wemb = Wo .* emb ----------------
__global__ __launch_bounds__(256) void emb_kernel(
    const float* __restrict__ x, const float* __restrict__ Wemb,
    const float* __restrict__ Wo)
{
    __shared__ float sx[16][68];
    __shared__ float sw[16][36];
    int tid = threadIdx.x;
    int m0 = blockIdx.x * 64;
    int n0 = blockIdx.y * 32;
    int tx = tid & 15, ty = tid >> 4;
    int tm0 = tx * 4, tn0 = ty * 2;

    float acc[4][2];
#pragma unroll
    for (int q = 0; q < 4; q++) { acc[q][0] = 0.f; acc[q][1] = 0.f; }

    for (int kt = 0; kt < DD; kt += 16) {
        {
            int e = tid * 4; int m = e >> 4; int k = e & 15;
            float4 v = *(const float4*)(x + (size_t)(m0 + m) * DD + kt + k);
            sx[k][m] = v.x; sx[k+1][m] = v.y; sx[k+2][m] = v.z; sx[k+3][m] = v.w;
        }
        {
            int e = tid * 2; int n = e >> 4; int k = e & 15;
            float2 v = *(const float2*)(Wemb + (size_t)(n0 + n) * DD + kt + k);
            sw[k][n] = v.x; sw[k+1][n] = v.y;
        }
        __syncthreads();
#pragma unroll
        for (int k = 0; k < 16; k++) {
            float a0 = sx[k][tm0], a1 = sx[k][tm0+1], a2 = sx[k][tm0+2], a3 = sx[k][tm0+3];
            float b0 = sw[k][tn0], b1 = sw[k][tn0+1];
            acc[0][0] += a0*b0; acc[0][1] += a0*b1;
            acc[1][0] += a1*b0; acc[1][1] += a1*b1;
            acc[2][0] += a2*b0; acc[2][1] += a2*b1;
            acc[3][0] += a3*b0; acc[3][1] += a3*b1;
        }
        __syncthreads();
    }
#pragma unroll
    for (int q = 0; q < 4; q++)
#pragma unroll
        for (int r = 0; r < 2; r++) {
            int m = m0 + tm0 + q, n = n0 + tn0 + r;
            float v = acc[q][r];
            g_emb [m*EE + n] = v;
            g_wemb[m*EE + n] = v * Wo[n];
        }
}

// ---------------- Kernel 2: GX = emb @ Wih^T + bih (both GRUs) ----------------
__global__ __launch_bounds__(256) void gx_kernel(
    const float* __restrict__ Wih_a, const float* __restrict__ Wih_b,
    const float* __restrict__ bih_a, const float* __restrict__ bih_b)
{
    __shared__ float se [16][68];
    __shared__ float sw2[16][68];
    int tid = threadIdx.x;
    int m0 = blockIdx.x * 64;
    int n0 = blockIdx.y * 64;
    int tx = tid & 15, ty = tid >> 4;
    int tm0 = tx * 4, tn0 = ty * 4;

    const float* W; const float* bi; float* out; int nb;
    if (n0 < GG) { W = Wih_a; bi = bih_a; out = g_GXa; nb = n0; }
    else         { W = Wih_b; bi = bih_b; out = g_GXb; nb = n0 - GG; }

    float acc[4][4];
#pragma unroll
    for (int q = 0; q < 4; q++)
#pragma unroll
        for (int r = 0; r < 4; r++) acc[q][r] = 0.f;

    for (int kt = 0; kt < EE; kt += 16) {
        {
            int e = tid * 4; int m = e >> 4; int k = e & 15;
            float4 v = *(const float4*)(g_emb + (size_t)(m0 + m) * EE + kt + k);
            se[k][m] = v.x; se[k+1][m] = v.y; se[k+2][m] = v.z; se[k+3][m] = v.w;
        }
        {
            int e = tid * 4; int n = e >> 4; int k = e & 15;
            float4 v = *(const float4*)(W + (size_t)(nb + n) * EE + kt + k);
            sw2[k][n] = v.x; sw2[k+1][n] = v.y; sw2[k+2][n] = v.z; sw2[k+3][n] = v.w;
        }
        __syncthreads();
#pragma unroll
        for (int k = 0; k < 16; k++) {
            float a[4], b[4];
#pragma unroll
            for (int q = 0; q < 4; q++) a[q] = se[k][tm0+q];
#pragma unroll
            for (int r = 0; r < 4; r++) b[r] = sw2[k][tn0+r];
#pragma unroll
            for (int q = 0; q < 4; q++)
#pragma unroll
                for (int r = 0; r < 4; r++) acc[q][r] += a[q]*b[r];
        }
        __syncthreads();
    }
#pragma unroll
    for (int q = 0; q < 4; q++)
#pragma unroll
        for (int r = 0; r < 4; r++) {
            int m = m0 + tm0 + q, n = nb + tn0 + r;
            out[(size_t)m*GG + n] = acc[q][r] + bi[n];
        }
}

// ---------------- Kernel 3: persistent GRU scan (EXACT R10, best: 589us) ------
__global__ __launch_bounds__(256, 1) void scan_kernel(
    const float* __restrict__ Whh_a, const float* __restrict__ Whh_b,
    const float* __restrict__ bhh_a, const float* __restrict__ bhh_b,
    int RA, int Rtot)
{
    extern __shared__ float smem[];
    float* shv = smem + OFF_H;

    unsigned sbase;
    asm("{ .reg .u64 t; cvta.to.shared.u64 t, %1; cvt.u32.u64 %0, t; }"
        : "=r"(sbase) : "l"(smem));
    unsigned shH = sbase + OFF_H * 4;      // h buffers: 2 x (8 x 132 floats)

    int tid = threadIdx.x;
    int lane = tid & 31, w = tid >> 5;
    int u = (w << 4) + (lane >> 1);
    int parity = lane & 1;
    int sqb = parity * 4;                  // my 4 seqs: sqb..sqb+3
    bool roleA = (blockIdx.x < RA);
    int rc = roleA ? blockIdx.x : blockIdx.x - RA;
    int R  = roleA ? RA : (Rtot - RA);

    const float* Whh = roleA ? Whh_a : Whh_b;
    const float* bhh = roleA ? bhh_a : bhh_b;
    const float* GX  = roleA ? g_GXa : g_GXb;
    float* HS        = roleA ? g_hsa : g_hsb;

    // stage all weight pairs into SMEM, ull2 entries e = (g*32+pp)*128 + u
    {
        const ull* W2 = (const ull*)Whh;
        ull* sz = (ull*)smem;
        for (int e = tid; e < 12288; e += 256) {
            int uu = e & 127;
            int pp = (e >> 7) & 31;
            int g  = e >> 12;
            const ull* src = W2 + (size_t)(g*128 + uu)*64 + 2*pp;
            sz[2*e]   = src[0];
            sz[2*e+1] = src[1];
        }
    }
    float bhr = bhh[u], bhz = bhh[128 + u], bhn = bhh[256 + u];

    unsigned wbR = sbase + (unsigned)u * 16;     // + pp*2048
    unsigned wbZ = wbR + 65536;
    unsigned wbN = wbZ + 65536;
    __syncthreads();

    for (int mIdx = 0;; mIdx++) {
        int g = mIdx*R + ((mIdx & 1) ? (R - 1 - rc) : rc);   // snake
        if (g >= NG8) break;

        int i  = 127 - (g >> 1);      // longest-first
        int b0 = (g & 1) * 8;

        __syncthreads();              // protect buffers vs previous group
        for (int idx = tid; idx < 8*132; idx += 256) shv[idx] = 0.f;  // buf0
        __syncthreads();

        float hold[4];
#pragma unroll
        for (int ss = 0; ss < 4; ss++) hold[ss] = 0.f;

        for (int k = 0; k <= i; k++) {
            int j = i - k;
            float gir[4], giz[4], gin[4];
#pragma unroll
            for (int ss = 0; ss < 4; ss++) {
                const float* p = GX + (size_t)((b0 + sqb + ss)*TT + j)*GG + u;
                gir[ss] = __ldg(p);
                giz[ss] = __ldg(p + 128);
                gin[ss] = __ldg(p + 256);
            }

            unsigned hb = shH + (unsigned)((k & 1) * 8*132) * 4
                              + (unsigned)sqb * 528;
            ull ar[4], az[4], an[4];
#pragma unroll
            for (int ss = 0; ss < 4; ss++) { ar[ss] = 0; az[ss] = 0; an[ss] = 0; }
#pragma unroll
            for (int pp = 0; pp < 32; pp++) {
                ull wr0, wr1, wz0, wz1, wn0, wn1;
                lds128v(wbR + (unsigned)pp*2048, wr0, wr1);
                lds128v(wbZ + (unsigned)pp*2048, wz0, wz1);
                lds128v(wbN + (unsigned)pp*2048, wn0, wn1);
#pragma unroll
                for (int ss = 0; ss < 4; ss++) {
                    ull p0, p1;
                    lds128v(hb + (unsigned)(ss*528 + pp*16), p0, p1);
                    ffma2(ar[ss], wr0, p0); ffma2(ar[ss], wr1, p1);
                    ffma2(az[ss], wz0, p0); ffma2(az[ss], wz1, p1);
                    ffma2(an[ss], wn0, p0); ffma2(an[ss], wn1, p1);
                }
            }

            int bufn = ((k + 1) & 1) * 8 * 132;
#pragma unroll
            for (int ss = 0; ss < 4; ss++) {
                int s = sqb + ss;
                float fr = pairsum(ar[ss]) + gir[ss] + bhr;
                float fz = pairsum(az[ss]) + giz[ss] + bhz;
                float fn = pairsum(an[ss]) + bhn;
                float rr = 0.5f + 0.5f * tanhhw(0.5f * fr);
                float zz = 0.5f + 0.5f * tanhhw(0.5f * fz);
                float nn = tanhhw(gin[ss] + rr * fn);
                float h2 = (1.f - zz)*nn + zz*hold[ss];
                hold[ss] = h2;
                shv[bufn + s*132 + u] = h2;
                HS[((size_t)k*NSEQ + (b0 + s)*TT + i)*HHN + u] = h2;
            }
            __syncthreads();
        } // k
    } // groups
}

// ---------------- Kernel 4: pre_alpha = 0.5*Wa·h_a + ba (512-thr CTAs) --------
__global__ __launch_bounds__(512) void alpha_kernel(
    const float* __restrict__ Wa, const float* __restrict__ ba)
{
    int r = blockIdx.x * 16 + (threadIdx.x >> 5);   // (k,n) flat
    int lane = threadIdx.x & 31;
    int k = r >> 11, n = r & 2047, i = n & 127;
    if (k > i) return;
    const float4 hv = *(const float4*)(g_hsa + ((size_t)k*NSEQ + n)*HHN + lane*4);
    const float4 wv = *(const float4*)(Wa + lane*4);
    float p = 0.5f*(hv.x*wv.x + hv.y*wv.y + hv.z*wv.z + hv.w*wv.w);
#pragma unroll
    for (int o = 16; o > 0; o >>= 1)
        p += __shfl_xor_sync(0xffffffffu, p, o);
    if (lane == 0) g_pa[(size_t)n*TT + k] = p + ba[0];
}

// ---------------- Kernel 5: beta GEMM + wemb dot -> s[n][k] -------------------
// R10 layout/patterns; phase widened 16 -> 32 k-elements (half the barriers).
__global__ __launch_bounds__(256) void beta_kernel(
    const float* __restrict__ Wb, const float* __restrict__ bb)
{
    int k  = blockIdx.x;          // 0..127
    int nb = blockIdx.y;          // 0..31
    int i0 = (nb & 1) * 64;
    if (i0 + 63 < k) return;
    int n0 = nb * 64;
    int b  = n0 >> 7;

    __shared__ float shh[32][68];
    __shared__ float sww[32][132];
    __shared__ float red[64][17];

    int tid = threadIdx.x;
    int tx = tid & 15, ty = tid >> 4;
    int r0 = tx * 4, e0 = ty * 8;

    const float* hb = g_hsb + ((size_t)k*NSEQ + n0)*HHN;

    ull acc2[4][4];
#pragma unroll
    for (int q = 0; q < 4; q++)
#pragma unroll
        for (int e = 0; e < 4; e++) acc2[q][e] = 0;

    for (int kt = 0; kt < HHN; kt += 32) {
#pragma unroll
        for (int rep = 0; rep < 2; rep++) {
            int ko = kt + rep*16;
            {
                int e = tid * 4; int rr = e >> 4; int h = e & 15;
                float4 v = *(const float4*)(hb + (size_t)rr*HHN + ko + h);
                shh[rep*16+h][rr] = v.x;   shh[rep*16+h+1][rr] = v.y;
                shh[rep*16+h+2][rr] = v.z; shh[rep*16+h+3][rr] = v.w;
            }
            {
                int e2 = tid * 8; int ee = e2 >> 4; int h = e2 & 15;
                float4 v0 = *(const float4*)(Wb + (size_t)ee*HHN + ko + h);
                float4 v1 = *(const float4*)(Wb + (size_t)ee*HHN + ko + h + 4);
                sww[rep*16+h  ][ee] = 0.5f*v0.x; sww[rep*16+h+1][ee] = 0.5f*v0.y;
                sww[rep*16+h+2][ee] = 0.5f*v0.z; sww[rep*16+h+3][ee] = 0.5f*v0.w;
                sww[rep*16+h+4][ee] = 0.5f*v1.x; sww[rep*16+h+5][ee] = 0.5f*v1.y;
                sww[rep*16+h+6][ee] = 0.5f*v1.z; sww[rep*16+h+7][ee] = 0.5f*v1.w;
            }
        }
        __syncthreads();
#pragma unroll
        for (int kk = 0; kk < 32; kk++) {
            ull av[4], bv[4];
#pragma unroll
            for (int q = 0; q < 4; q++) av[q] = dup2(shh[kk][r0+q]);
            const ull* bp = (const ull*)&sww[kk][e0];
#pragma unroll
            for (int e = 0; e < 4; e++) bv[e] = bp[e];
#pragma unroll
            for (int q = 0; q < 4; q++)
#pragma unroll
                for (int e = 0; e < 4; e++) ffma2(acc2[q][e], av[q], bv[e]);
        }
        __syncthreads();
    }

    float bbv[8];
#pragma unroll
    for (int e = 0; e < 8; e++) bbv[e] = bb[e0 + e];

#pragma unroll
    for (int q = 0; q < 4; q++) {
        int n = n0 + r0 + q;
        int i = n & 127;
        int j = i - k;
        const float* wm = g_wemb + ((size_t)b*TT + (j >= 0 ? j : 0))*EE + e0;
        float p = 0.f;
#pragma unroll
        for (int e = 0; e < 4; e++) {
            float lo = __uint_as_float((unsigned)acc2[q][e]);
            float hi = __uint_as_float((unsigned)(acc2[q][e] >> 32));
            p += tanhhw(lo + bbv[2*e])   * wm[2*e];
            p += tanhhw(hi + bbv[2*e+1]) * wm[2*e+1];
        }
        red[r0 + q][ty] = p;
    }
    __syncthreads();
    if (tid < 64) {
        float v = 0.f;
#pragma unroll
        for (int t = 0; t < 16; t++) v += red[tid][t];
        int n = n0 + tid;
        int i = n & 127;
        if (k <= i) g_sv[(size_t)n*TT + k] = v;
    }
}

// ---------------- Kernel 6: masked softmax combine ----------------
__global__ __launch_bounds__(256) void combine_kernel(
    const float* __restrict__ bo, float* __restrict__ out)
{
    int w = blockIdx.x * 8 + (threadIdx.x >> 5);
    int lane = threadIdx.x & 31;
    if (w >= NSEQ) return;
    int i = w & 127;
    float num = 0.f, den = 0.f;
    for (int k = lane; k <= i; k += 32) {
        float ev = __expf(g_pa[(size_t)w*TT + k]);
        num += ev * g_sv[(size_t)w*TT + k];
        den += ev;
    }
#pragma unroll
    for (int o = 16; o > 0; o >>= 1) {
        num += __shfl_xor_sync(0xffffffffu, num, o);
        den += __shfl_xor_sync(0xffffffffu, den, o);
    }
    if (lane == 0) out[w] = num / den + bo[0];
}

// ---------------- launch ----------------
extern "C" void kernel_launch(void* const* d_in, const int* in_sizes, int n_in,
                              void* d_out, int out_size)
{
    const float* x     = (const float*)d_in[0];
    const float* Wemb  = (const float*)d_in[1];
    const float* Wih_a = (const float*)d_in[2];
    const float* Whh_a = (const float*)d_in[3];
    const float* bih_a = (const float*)d_in[4];
    const float* bhh_a = (const float*)d_in[5];
    const float* Wa    = (const float*)d_in[6];
    const float* ba    = (const float*)d_in[7];
    const float* Wih_b = (const float*)d_in[8];
    const float* Whh_b = (const float*)d_in[9];
    const float* bih_b = (const float*)d_in[10];
    const float* bhh_b = (const float*)d_in[11];
    const float* Wb    = (const float*)d_in[12];
    const float* bb    = (const float*)d_in[13];
    const float* Wo    = (const float*)d_in[14];
    const float* bo    = (const float*)d_in[15];
    float* out = (float*)d_out;

    int dev = 0;
    cudaGetDevice(&dev);
    int sms = 148;
    cudaDeviceGetAttribute(&sms, cudaDevAttrMultiProcessorCount, dev);
    int RA = sms / 2;

    size_t smem_bytes = (size_t)SMEM_FLOATS * sizeof(float);
    cudaFuncSetAttribute(scan_kernel,
                         cudaFuncAttributeMaxDynamicSharedMemorySize,
                         (int)smem_bytes);

    emb_kernel<<<dim3(32, 4), 256>>>(x, Wemb, Wo);
    gx_kernel<<<dim3(32, 12), 256>>>(Wih_a, Wih_b, bih_a, bih_b);
    scan_kernel<<<sms, 256, smem_bytes>>>(Whh_a, Whh_b, bhh_a, bhh_b, RA, sms);
    alpha_kernel<<<(NSEQ*TT)/16, 512>>>(Wa, ba);
    beta_kernel<<<dim3(TT, NSEQ/64), 256>>>(Wb, bb);
    combine_kernel<<<NSEQ/8, 256>>>(bo, out);
}